// round 2
// baseline (speedup 1.0000x reference)
#include <cuda_runtime.h>
#include <math.h>

#define NK   4096
#define D    256
#define NIN  32768
#define BM   128
#define BN   64
#define XSTRIDE 258
#define GATHER_BLOCKS 512
#define SX_ROWS 64

// scratch (no allocations allowed -> device globals)
__device__ float g_sw[NK];         // sum w^2 per code
__device__ float g_sx[NIN];        // sum x^2 per row, ref-exact sequential order
__device__ int   g_idx[NIN];       // argmin index per row
__device__ int   g_counts[NK];     // histogram
__device__ float g_partial[GATHER_BLOCKS];

// ---------------------------------------------------------------------------
__global__ void k_zero() {
    int t = blockIdx.x * blockDim.x + threadIdx.x;
    if (t < NK) g_counts[t] = 0;
}

// one warp per codebook row: sum w^2 (order-insensitive; value ~5e-6)
__global__ void k_wsq(const float* __restrict__ W) {
    int warp = (blockIdx.x * blockDim.x + threadIdx.x) >> 5;
    int lane = threadIdx.x & 31;
    if (warp >= NK) return;
    const float4* w4 = (const float4*)(W + (size_t)warp * D);
    float s = 0.f;
    #pragma unroll
    for (int i = 0; i < 2; i++) {
        float4 v = w4[lane + i * 32];
        s += v.x*v.x + v.y*v.y + v.z*v.z + v.w*v.w;
    }
    #pragma unroll
    for (int off = 16; off; off >>= 1) s += __shfl_down_sync(0xffffffffu, s, off);
    if (lane == 0) g_sw[warp] = s;
}

// ---------------------------------------------------------------------------
// sum(x^2) per row, replicating XLA-CPU strict-IEEE scalar reduction:
// s = fl(s + fl(x_i * x_i)), i ascending 0..255, single sequential chain.
__global__ void __launch_bounds__(256, 1)
k_sx(const float* __restrict__ X) {
    __shared__ float tile[SX_ROWS * 257];
    int row0 = blockIdx.x * SX_ROWS;
    int tid = threadIdx.x;
    for (int idx = tid; idx < SX_ROWS * D; idx += 256) {
        int r = idx >> 8, c = idx & 255;
        tile[r * 257 + c] = X[(size_t)(row0 + r) * D + c];
    }
    __syncthreads();
    if (tid < SX_ROWS) {
        const float* p = tile + tid * 257;
        float s = 0.f;
        #pragma unroll 8
        for (int i = 0; i < D; i++) {
            float v = p[i];
            s = __fadd_rn(s, __fmul_rn(v, v));
        }
        g_sx[row0 + tid] = s;
    }
}

// ---------------------------------------------------------------------------
// Fused GEMM + argmin over d_k = fl( fl(sx + sw_k) - fl(2*dot_k) ).
// dot accumulated as a single fma chain over d=0..255 ascending (Eigen order).
// Strict '<' with ascending k scan, then lowest-index tie-break across lanes
// -> matches jnp.argmin on the quantized distances.
extern "C" __global__ void __launch_bounds__(256, 1)
k_argmin(const float* __restrict__ X, const float* __restrict__ W) {
    extern __shared__ float smem[];
    float* Xs  = smem;                   // [BM][XSTRIDE]
    float* WsT = smem + BM * XSTRIDE;    // [D][BN]

    int tid  = threadIdx.x;
    int row0 = blockIdx.x * BM;

    {
        const float4* Xg = (const float4*)(X + (size_t)row0 * D);
        for (int i = tid; i < BM * D / 4; i += 256) {
            float4 v = Xg[i];
            int r  = i / (D / 4);
            int dc = (i % (D / 4)) * 4;
            float* p = Xs + r * XSTRIDE + dc;
            p[0] = v.x; p[1] = v.y; p[2] = v.z; p[3] = v.w;
        }
    }

    int ty = tid >> 4, tx = tid & 15;

    float sxr[8];
    #pragma unroll
    for (int r = 0; r < 8; r++) sxr[r] = g_sx[row0 + ty * 8 + r];

    float bestd[8];
    int   besti[8];
    #pragma unroll
    for (int r = 0; r < 8; r++) { bestd[r] = 3.4e38f; besti[r] = 0; }

    int code = tid & 63, dg = tid >> 6;

    for (int chunk = 0; chunk < NK / BN; chunk++) {
        __syncthreads();
        const float* Wrow = W + (size_t)(chunk * BN + code) * D + dg * 64;
        #pragma unroll
        for (int j = 0; j < 64; j += 4) {
            float4 v = *(const float4*)(Wrow + j);
            int d = dg * 64 + j;
            WsT[(d + 0) * BN + code] = v.x;
            WsT[(d + 1) * BN + code] = v.y;
            WsT[(d + 2) * BN + code] = v.z;
            WsT[(d + 3) * BN + code] = v.w;
        }
        __syncthreads();

        float acc[8][4];
        #pragma unroll
        for (int r = 0; r < 8; r++)
            acc[r][0] = acc[r][1] = acc[r][2] = acc[r][3] = 0.f;

        const float* xbase = Xs + (ty * 8) * XSTRIDE;
        #pragma unroll 8
        for (int d = 0; d < D; d++) {
            float4 b = *(const float4*)(WsT + d * BN + tx * 4);
            #pragma unroll
            for (int r = 0; r < 8; r++) {
                float a = xbase[r * XSTRIDE + d];
                acc[r][0] = fmaf(a, b.x, acc[r][0]);
                acc[r][1] = fmaf(a, b.y, acc[r][1]);
                acc[r][2] = fmaf(a, b.z, acc[r][2]);
                acc[r][3] = fmaf(a, b.w, acc[r][3]);
            }
        }

        #pragma unroll
        for (int c = 0; c < 4; c++) {
            int kc = chunk * BN + tx * 4 + c;
            float swv = g_sw[kc];
            #pragma unroll
            for (int r = 0; r < 8; r++) {
                float u = __fadd_rn(sxr[r], swv);            // fl(sx + sw)
                float t = __fmul_rn(2.0f, acc[r][c]);         // fl(2*dot)
                float dd = __fsub_rn(u, t);                   // fl(u - t)
                if (dd < bestd[r]) { bestd[r] = dd; besti[r] = kc; }
            }
        }
    }

    #pragma unroll
    for (int r = 0; r < 8; r++) {
        float v = bestd[r];
        int   i = besti[r];
        #pragma unroll
        for (int off = 8; off >= 1; off >>= 1) {
            float ov = __shfl_down_sync(0xffffffffu, v, off, 16);
            int   oi = __shfl_down_sync(0xffffffffu, i, off, 16);
            if (ov < v || (ov == v && oi < i)) { v = ov; i = oi; }
        }
        if (tx == 0) g_idx[row0 + ty * 8 + r] = i;
    }
}

// ---------------------------------------------------------------------------
// quantized_st = fl(x + fl(q - x)) elementwise (ref straight-through ops),
// plus sum (q-x)^2 partials and histogram counts.
__global__ void k_gather(const float* __restrict__ X, const float* __restrict__ W,
                         float* __restrict__ out) {
    __shared__ float wsum[8];
    int lane = threadIdx.x & 31, warp = threadIdx.x >> 5;
    int gwarp = blockIdx.x * 8 + warp;
    float s = 0.f;
    #pragma unroll
    for (int j = 0; j < 8; j++) {
        int row = gwarp * 8 + j;
        int k = g_idx[row];
        const float4* wp = (const float4*)(W + (size_t)k * D);
        const float4* xp = (const float4*)(X + (size_t)row * D);
        float* op = out + 1 + (size_t)row * D;
        for (int i = lane; i < D / 4; i += 32) {
            float4 w = wp[i], x = xp[i];
            float dx = __fsub_rn(w.x, x.x), dy = __fsub_rn(w.y, x.y);
            float dz = __fsub_rn(w.z, x.z), dw = __fsub_rn(w.w, x.w);
            op[i * 4 + 0] = __fadd_rn(x.x, dx);
            op[i * 4 + 1] = __fadd_rn(x.y, dy);
            op[i * 4 + 2] = __fadd_rn(x.z, dz);
            op[i * 4 + 3] = __fadd_rn(x.w, dw);
            s += dx * dx + dy * dy + dz * dz + dw * dw;
        }
        if (lane == 0) atomicAdd(&g_counts[k], 1);
    }
    #pragma unroll
    for (int off = 16; off; off >>= 1) s += __shfl_down_sync(0xffffffffu, s, off);
    if (lane == 0) wsum[warp] = s;
    __syncthreads();
    if (threadIdx.x == 0) {
        float t = 0.f;
        #pragma unroll
        for (int w = 0; w < 8; w++) t += wsum[w];
        g_partial[blockIdx.x] = t;
    }
}

// ---------------------------------------------------------------------------
__global__ void k_finalize(float* out, int out_size) {
    __shared__ float red[256];
    int tid = threadIdx.x;
    float e = 0.f;
    for (int k = tid; k < NK; k += 256) {
        float p = (float)g_counts[k] * (1.0f / (float)NIN);
        e += p * logf(p + 1e-10f);
    }
    red[tid] = e;
    __syncthreads();
    for (int off = 128; off; off >>= 1) {
        if (tid < off) red[tid] += red[tid + off];
        __syncthreads();
    }
    if (tid == 0) {
        float ssum = 0.f;
        for (int b = 0; b < GATHER_BLOCKS; b++) ssum += g_partial[b];
        out[0] = 1.25f * ssum / (float)(NIN * D);
        out[out_size - 1] = expf(-red[0]);
    }
}

// ---------------------------------------------------------------------------
extern "C" void kernel_launch(void* const* d_in, const int* in_sizes, int n_in,
                              void* d_out, int out_size) {
    const float* X = (const float*)d_in[0];   // inputs [32768, 256]
    const float* W = (const float*)d_in[1];   // codebook [4096, 256]
    float* out = (float*)d_out;               // [loss, quantized_st, perplexity]

    const int smem_bytes = (BM * XSTRIDE + D * BN) * (int)sizeof(float);
    cudaFuncSetAttribute((const void*)k_argmin,
                         cudaFuncAttributeMaxDynamicSharedMemorySize, smem_bytes);

    k_zero<<<(NK + 255) / 256, 256>>>();
    k_wsq<<<NK / 8, 256>>>(W);
    k_sx<<<NIN / SX_ROWS, 256>>>(X);
    k_argmin<<<NIN / BM, 256, smem_bytes>>>(X, W);
    k_gather<<<GATHER_BLOCKS, 256>>>(X, W, out);
    k_finalize<<<1, 256>>>(out, out_size);
}